// round 2
// baseline (speedup 1.0000x reference)
#include <cuda_runtime.h>
#include <cuda_bf16.h>

// AttentionGate fused kernel (fp32 exact, f32x2-packed FFMA2 path)
//
// psi = sigmoid(Wpsi . relu(Wg@g + Wx@x));  out = x * psi
// B=2, CF=CG=64, CI=32, DHW=64^3=262144.
//
// Each thread processes ONE PAIR of consecutive voxels, packed into f32x2
// (64-bit) registers, so every fma.rn.f32x2 does 2 voxels' worth of work.
// Weights live in shared memory pre-duplicated as (w,w) pairs -> the inner
// loop is LDS.128 (two packed weights) + 2x FFMA2, no packing ALU.

#define DHW   262144
#define HALFV 131072      // DHW/2 (float2 elements per channel-plane)
#define NCF   64
#define NCG   64
#define NCI   32
#define NPAIR 262144      // B * DHW / 2 total voxel pairs

typedef unsigned long long u64;

__device__ __forceinline__ u64 ffma2(u64 a, u64 b, u64 c) {
    u64 d;
    asm("fma.rn.f32x2 %0, %1, %2, %3;" : "=l"(d) : "l"(a), "l"(b), "l"(c));
    return d;
}
__device__ __forceinline__ u64 fmul2(u64 a, u64 b) {
    u64 d;
    asm("mul.rn.f32x2 %0, %1, %2;" : "=l"(d) : "l"(a), "l"(b));
    return d;
}
__device__ __forceinline__ u64 pack2(float lo, float hi) {
    u64 r;
    asm("mov.b64 %0, {%1, %2};" : "=l"(r) : "f"(lo), "f"(hi));
    return r;
}
__device__ __forceinline__ float2 unpack2(u64 v) {
    float2 r;
    asm("mov.b64 {%0, %1}, %2;" : "=f"(r.x), "=f"(r.y) : "l"(v));
    return r;
}

__global__ __launch_bounds__(256, 4)
void attn_gate_kernel(const float* __restrict__ x,
                      const float* __restrict__ g,
                      const float* __restrict__ Wg,
                      const float* __restrict__ Wx,
                      const float* __restrict__ Wpsi,
                      float* __restrict__ out)
{
    // Combined weight matrix, transposed to [k][o], each weight stored as the
    // packed pair (w,w) so it feeds fma.rn.f32x2 directly.
    // k in [0,64)  -> Wg column k; k in [64,128) -> Wx column k-64.
    __shared__ u64   Wc[128][NCI];     // 32 KiB
    __shared__ float wpsi_s[NCI];

    for (int i = threadIdx.x; i < 128 * NCI; i += blockDim.x) {
        int k = i >> 5;          // 0..127
        int o = i & 31;          // 0..31
        float w = (k < NCG) ? Wg[o * NCG + k] : Wx[o * NCF + (k - NCG)];
        Wc[k][o] = pack2(w, w);
    }
    if (threadIdx.x < NCI) wpsi_s[threadIdx.x] = Wpsi[threadIdx.x];
    __syncthreads();

    int p = blockIdx.x * blockDim.x + threadIdx.x;   // voxel-pair index
    if (p >= NPAIR) return;
    int b  = p >> 17;            // batch (HALFV = 2^17)
    int sp = p & (HALFV - 1);    // pair index within spatial volume

    // Channel stride in float2/u64 units is HALFV.
    const u64* g2 = (const u64*)g + (size_t)b * NCG * HALFV + sp;
    const u64* x2 = (const u64*)x + (size_t)b * NCF * HALFV + sp;
    u64*       o2 = (u64*)out     + (size_t)b * NCF * HALFV + sp;

    u64 acc[NCI];
    #pragma unroll
    for (int o = 0; o < NCI; o++) acc[o] = 0ULL;   // bit pattern == (0.f, 0.f)

    // ---- g projection: acc[o] += Wg[o][k] * g[k] (2 voxels packed) ----
    #pragma unroll 4
    for (int k = 0; k < NCG; k++) {
        u64 v = g2[(size_t)k * HALFV];
        const ulonglong2* wr = (const ulonglong2*)(&Wc[k][0]);
        #pragma unroll
        for (int o = 0; o < NCI / 2; o++) {
            ulonglong2 w = wr[o];                 // LDS.128: two packed weights
            acc[2 * o]     = ffma2(w.x, v, acc[2 * o]);
            acc[2 * o + 1] = ffma2(w.y, v, acc[2 * o + 1]);
        }
    }

    // ---- x projection: acc[o] += Wx[o][k] * x[k] ----
    #pragma unroll 4
    for (int k = 0; k < NCF; k++) {
        u64 v = x2[(size_t)k * HALFV];
        const ulonglong2* wr = (const ulonglong2*)(&Wc[NCG + k][0]);
        #pragma unroll
        for (int o = 0; o < NCI / 2; o++) {
            ulonglong2 w = wr[o];
            acc[2 * o]     = ffma2(w.x, v, acc[2 * o]);
            acc[2 * o + 1] = ffma2(w.y, v, acc[2 * o + 1]);
        }
    }

    // ---- relu + Wpsi dot + sigmoid (scalar; negligible vs main loop) ----
    float sx = 0.f, sy = 0.f;
    #pragma unroll
    for (int o = 0; o < NCI; o++) {
        float2 a = unpack2(acc[o]);
        float  w = wpsi_s[o];
        sx = fmaf(fmaxf(a.x, 0.f), w, sx);
        sy = fmaf(fmaxf(a.y, 0.f), w, sy);
    }
    float px = 1.f / (1.f + __expf(-sx));
    float py = 1.f / (1.f + __expf(-sy));
    u64 psi = pack2(px, py);

    // ---- out[c] = x[c] * psi  (x re-read: mostly L2-resident) ----
    #pragma unroll 8
    for (int c = 0; c < NCF; c++) {
        u64 xv = x2[(size_t)c * HALFV];
        o2[(size_t)c * HALFV] = fmul2(xv, psi);
    }
}

extern "C" void kernel_launch(void* const* d_in, const int* in_sizes, int n_in,
                              void* d_out, int out_size)
{
    const float* x    = (const float*)d_in[0];
    const float* g    = (const float*)d_in[1];
    const float* Wg   = (const float*)d_in[2];
    const float* Wx   = (const float*)d_in[3];
    const float* Wpsi = (const float*)d_in[4];
    float* out = (float*)d_out;

    // 262144 voxel pairs / 256 threads = 1024 blocks (exact cover)
    attn_gate_kernel<<<1024, 256>>>(x, g, Wg, Wx, Wpsi, out);
}

// round 3
// speedup vs baseline: 2.0613x; 2.0613x over previous
#include <cuda_runtime.h>
#include <cuda_bf16.h>

// AttentionGate fused kernel, round 3: split-CI to kill register spills.
//
// psi = sigmoid(Wpsi . relu(Wg@g + Wx@x));  out = x * psi
// B=2, CF=CG=64, CI=32, DHW=64^3=262144.
//
// Lane pair (2i, 2i+1) shares one voxel PAIR (two consecutive voxels packed
// as f32x2). Lane 2i computes CI channels [0,16), lane 2i+1 computes [16,32).
// acc[16] u64 = 32 regs -> no spills (round 2 spilled with acc[32] = 64 regs
// under a 64-reg cap: L1 71%, 1.2GB DRAM traffic, 618us).
// psi partial dots are summed across the lane pair via shfl_xor(1); the 64
// output channels are split 32/32 between the two lanes in the epilogue.

#define HALFV 131072      // DHW/2 (f32x2 elements per channel-plane)
#define NCI   32
#define NPAIR 262144      // B * DHW / 2 voxel pairs

typedef unsigned long long u64;

__device__ __forceinline__ u64 ffma2(u64 a, u64 b, u64 c) {
    u64 d;
    asm("fma.rn.f32x2 %0, %1, %2, %3;" : "=l"(d) : "l"(a), "l"(b), "l"(c));
    return d;
}
__device__ __forceinline__ u64 fmul2(u64 a, u64 b) {
    u64 d;
    asm("mul.rn.f32x2 %0, %1, %2;" : "=l"(d) : "l"(a), "l"(b));
    return d;
}
__device__ __forceinline__ u64 pack2(float lo, float hi) {
    u64 r;
    asm("mov.b64 %0, {%1, %2};" : "=l"(r) : "f"(lo), "f"(hi));
    return r;
}
__device__ __forceinline__ float2 unpack2(u64 v) {
    float2 r;
    asm("mov.b64 {%0, %1}, %2;" : "=f"(r.x), "=f"(r.y) : "l"(v));
    return r;
}

__global__ __launch_bounds__(256, 3)
void attn_gate_kernel(const float* __restrict__ x,
                      const float* __restrict__ g,
                      const float* __restrict__ Wg,
                      const float* __restrict__ Wx,
                      const float* __restrict__ Wpsi,
                      float* __restrict__ out)
{
    // Combined weights, [k][o] layout, each stored as packed (w,w) f32x2.
    // k in [0,64) -> Wg column k;  k in [64,128) -> Wx column k-64.
    __shared__ u64   Wc[128][NCI];     // 32 KiB
    __shared__ float wpsi_s[NCI];

    for (int i = threadIdx.x; i < 128 * NCI; i += 256) {
        int k = i >> 5;          // 0..127
        int o = i & 31;          // 0..31
        float w = (k < 64) ? Wg[o * 64 + k] : Wx[o * 64 + (k - 64)];
        Wc[k][o] = pack2(w, w);
    }
    if (threadIdx.x < NCI) wpsi_s[threadIdx.x] = Wpsi[threadIdx.x];
    __syncthreads();

    int t  = blockIdx.x * 256 + threadIdx.x;
    int p  = t >> 1;             // voxel-pair index (shared by lane pair)
    int h  = t & 1;              // CI-half: 0 -> channels 0..15, 1 -> 16..31
    int b  = p >> 17;            // batch (HALFV = 2^17)
    int sp = p & (HALFV - 1);    // pair index within spatial volume

    const u64* g2 = (const u64*)g + (size_t)(b * 64) * HALFV + sp;
    const u64* x2 = (const u64*)x + (size_t)(b * 64) * HALFV + sp;
    u64*       o2 = (u64*)out     + (size_t)(b * 64) * HALFV + sp;

    // This lane's 16 weight pairs per k-row (8x LDS.128, broadcast per half-warp)
    const ulonglong2* wr = (const ulonglong2*)(&Wc[0][h * 16]);

    u64 acc[16];
    #pragma unroll
    for (int o = 0; o < 16; o++) acc[o] = 0ULL;   // (0.f, 0.f)

    // ---- g projection ----
    const u64* gp = g2;
    #pragma unroll 2
    for (int k = 0; k < 64; k++) {
        u64 v = *gp;  gp += HALFV;
        #pragma unroll
        for (int o = 0; o < 8; o++) {
            ulonglong2 w = wr[o];
            acc[2 * o]     = ffma2(w.x, v, acc[2 * o]);
            acc[2 * o + 1] = ffma2(w.y, v, acc[2 * o + 1]);
        }
        wr += NCI / 2;   // next k row (16 ulonglong2 per row)
    }

    // ---- x projection ----
    const u64* xp = x2;
    #pragma unroll 2
    for (int k = 0; k < 64; k++) {
        u64 v = *xp;  xp += HALFV;
        #pragma unroll
        for (int o = 0; o < 8; o++) {
            ulonglong2 w = wr[o];
            acc[2 * o]     = ffma2(w.x, v, acc[2 * o]);
            acc[2 * o + 1] = ffma2(w.y, v, acc[2 * o + 1]);
        }
        wr += NCI / 2;
    }

    // ---- relu + partial Wpsi dot (this lane's 16 channels) ----
    float sx = 0.f, sy = 0.f;
    #pragma unroll
    for (int o = 0; o < 16; o++) {
        float2 a = unpack2(acc[o]);
        float  w = wpsi_s[h * 16 + o];
        sx = fmaf(fmaxf(a.x, 0.f), w, sx);
        sy = fmaf(fmaxf(a.y, 0.f), w, sy);
    }
    // Combine lane-pair partials -> full dot in both lanes
    sx += __shfl_xor_sync(0xffffffffu, sx, 1);
    sy += __shfl_xor_sync(0xffffffffu, sy, 1);

    float px = 1.f / (1.f + __expf(-sx));
    float py = 1.f / (1.f + __expf(-sy));
    u64 psi = pack2(px, py);

    // ---- out[c] = x[c] * psi : lane half h writes channels [h*32, h*32+32) ----
    const u64* xw = x2 + (size_t)(h * 32) * HALFV;
    u64*       ow = o2 + (size_t)(h * 32) * HALFV;
    #pragma unroll 4
    for (int c = 0; c < 32; c++) {
        ow[(size_t)c * HALFV] = fmul2(xw[(size_t)c * HALFV], psi);
    }
}

extern "C" void kernel_launch(void* const* d_in, const int* in_sizes, int n_in,
                              void* d_out, int out_size)
{
    const float* x    = (const float*)d_in[0];
    const float* g    = (const float*)d_in[1];
    const float* Wg   = (const float*)d_in[2];
    const float* Wx   = (const float*)d_in[3];
    const float* Wpsi = (const float*)d_in[4];
    float* out = (float*)d_out;

    // 2 threads per voxel pair: 524288 threads = 2048 blocks of 256
    attn_gate_kernel<<<2048, 256>>>(x, g, Wg, Wx, Wpsi, out);
}

// round 8
// speedup vs baseline: 2.3832x; 1.1562x over previous
#include <cuda_runtime.h>
#include <cuda_bf16.h>

// AttentionGate fused kernel, round 6: round-4 retile with CORRECT grid.
// (Round-4/5 crashed: 2048 blocks covered 2x the voxel pairs -> OOB.
//  Each warp covers exactly 32 pairs; 262144 pairs / 32 = 8192 warps
//  = 1024 blocks of 256 threads.)
//
// psi = sigmoid(Wpsi . relu(Wg@g + Wx@x));  out = x * psi
// B=2, CF=CG=64, CI=32, DHW=64^3=262144.
//
// Each thread owns 4 voxel-pair streams x 8 CI channels; each weight
// LDS.128 feeds 8 FFMA2 (vs 2 in round 3 -> LDS issue /4). CI split
// 4-ways across lanes (lane&3); psi partials combine via 2x shfl_xor.
// Weight rows q-interleaved so each lane-quarter's 16B chunks are
// contiguous -> conflict-free LDS.

#define HALFV 131072      // DHW/2 (f32x2 elements per channel-plane)

typedef unsigned long long u64;

__device__ __forceinline__ u64 ffma2(u64 a, u64 b, u64 c) {
    u64 d;
    asm("fma.rn.f32x2 %0, %1, %2, %3;" : "=l"(d) : "l"(a), "l"(b), "l"(c));
    return d;
}
__device__ __forceinline__ u64 fmul2(u64 a, u64 b) {
    u64 d;
    asm("mul.rn.f32x2 %0, %1, %2;" : "=l"(d) : "l"(a), "l"(b));
    return d;
}
__device__ __forceinline__ u64 pack2(float lo, float hi) {
    u64 r;
    asm("mov.b64 %0, {%1, %2};" : "=l"(r) : "f"(lo), "f"(hi));
    return r;
}
__device__ __forceinline__ float2 unpack2(u64 v) {
    float2 r;
    asm("mov.b64 {%0, %1}, %2;" : "=f"(r.x), "=f"(r.y) : "l"(v));
    return r;
}

__global__ __launch_bounds__(256, 2)
void attn_gate_kernel(const float* __restrict__ x,
                      const float* __restrict__ g,
                      const float* __restrict__ Wg,
                      const float* __restrict__ Wx,
                      const float* __restrict__ Wpsi,
                      float* __restrict__ out)
{
    // Wc[k] row layout (u64 units): chunk (4i+q) at u64 index 2*(4i+q)+lh
    // holds channel o = 8q + 2i + lh, packed (w,w).
    // k in [0,64) -> Wg column k; k in [64,128) -> Wx column k-64.
    __shared__ u64   Wc[128][32];      // 32 KiB
    __shared__ float wpsi_s[32];

    for (int idx = threadIdx.x; idx < 128 * 32; idx += 256) {
        int k = idx >> 5;
        int o = idx & 31;                       // channel
        int q = o >> 3, r = o & 7, i = r >> 1, lh = r & 1;
        float w = (k < 64) ? Wg[o * 64 + k] : Wx[o * 64 + (k - 64)];
        Wc[k][2 * (4 * i + q) + lh] = pack2(w, w);
    }
    if (threadIdx.x < 32) wpsi_s[threadIdx.x] = Wpsi[threadIdx.x];
    __syncthreads();

    int t    = blockIdx.x * 256 + threadIdx.x;
    int lane = t & 31;
    int wid  = t >> 5;           // global warp id (0..8191)
    int gl   = lane >> 2;        // spatial subgroup 0..7
    int q    = lane & 3;         // CI quarter: channels [8q, 8q+8)

    int pbase = wid * 32;                    // warp's first voxel pair
    int b     = pbase >> 17;                 // batch (HALFV = 2^17 pairs/batch)
    int sp    = (pbase & (HALFV - 1)) + gl;  // this thread's stream-0 pair

    // Streams j=0..3 are at sp + 8j (u64 offsets 0,8,16,24 -> 64B coalesced).
    const u64* g2 = (const u64*)g + (size_t)(b * 64) * HALFV + sp;
    const u64* x2 = (const u64*)x + (size_t)(b * 64) * HALFV + sp;
    u64*       o2 = (u64*)out     + (size_t)(b * 64) * HALFV + sp;

    u64 acc[8][4];               // [CI within quarter][stream]
    #pragma unroll
    for (int o = 0; o < 8; o++)
        #pragma unroll
        for (int j = 0; j < 4; j++) acc[o][j] = 0ULL;

    // ---- g projection (k = 0..63) ----
    {
        const u64* gp = g2;
        #pragma unroll 4
        for (int k = 0; k < 64; k++) {
            u64 v0 = gp[0], v1 = gp[8], v2 = gp[16], v3 = gp[24];
            const ulonglong2* wrow = (const ulonglong2*)(&Wc[k][0]) + q;
            #pragma unroll
            for (int i = 0; i < 4; i++) {
                ulonglong2 w = wrow[4 * i];     // channels 8q+2i, 8q+2i+1
                acc[2*i][0]   = ffma2(w.x, v0, acc[2*i][0]);
                acc[2*i][1]   = ffma2(w.x, v1, acc[2*i][1]);
                acc[2*i][2]   = ffma2(w.x, v2, acc[2*i][2]);
                acc[2*i][3]   = ffma2(w.x, v3, acc[2*i][3]);
                acc[2*i+1][0] = ffma2(w.y, v0, acc[2*i+1][0]);
                acc[2*i+1][1] = ffma2(w.y, v1, acc[2*i+1][1]);
                acc[2*i+1][2] = ffma2(w.y, v2, acc[2*i+1][2]);
                acc[2*i+1][3] = ffma2(w.y, v3, acc[2*i+1][3]);
            }
            gp += HALFV;
        }
    }

    // ---- x projection (k = 64..127) ----
    {
        const u64* xp = x2;
        #pragma unroll 4
        for (int k = 0; k < 64; k++) {
            u64 v0 = xp[0], v1 = xp[8], v2 = xp[16], v3 = xp[24];
            const ulonglong2* wrow = (const ulonglong2*)(&Wc[64 + k][0]) + q;
            #pragma unroll
            for (int i = 0; i < 4; i++) {
                ulonglong2 w = wrow[4 * i];
                acc[2*i][0]   = ffma2(w.x, v0, acc[2*i][0]);
                acc[2*i][1]   = ffma2(w.x, v1, acc[2*i][1]);
                acc[2*i][2]   = ffma2(w.x, v2, acc[2*i][2]);
                acc[2*i][3]   = ffma2(w.x, v3, acc[2*i][3]);
                acc[2*i+1][0] = ffma2(w.y, v0, acc[2*i+1][0]);
                acc[2*i+1][1] = ffma2(w.y, v1, acc[2*i+1][1]);
                acc[2*i+1][2] = ffma2(w.y, v2, acc[2*i+1][2]);
                acc[2*i+1][3] = ffma2(w.y, v3, acc[2*i+1][3]);
            }
            xp += HALFV;
        }
    }

    // ---- relu + partial Wpsi dot for this lane's 8 channels ----
    float sx[4] = {0.f, 0.f, 0.f, 0.f};
    float sy[4] = {0.f, 0.f, 0.f, 0.f};
    #pragma unroll
    for (int o = 0; o < 8; o++) {
        float wp = wpsi_s[8 * q + o];
        #pragma unroll
        for (int j = 0; j < 4; j++) {
            float2 a = unpack2(acc[o][j]);
            sx[j] = fmaf(fmaxf(a.x, 0.f), wp, sx[j]);
            sy[j] = fmaf(fmaxf(a.y, 0.f), wp, sy[j]);
        }
    }
    // Reduce across the 4 lanes (q=0..3) sharing each pair.
    u64 psi[4];
    #pragma unroll
    for (int j = 0; j < 4; j++) {
        sx[j] += __shfl_xor_sync(0xffffffffu, sx[j], 1);
        sx[j] += __shfl_xor_sync(0xffffffffu, sx[j], 2);
        sy[j] += __shfl_xor_sync(0xffffffffu, sy[j], 1);
        sy[j] += __shfl_xor_sync(0xffffffffu, sy[j], 2);
        float px = 1.f / (1.f + __expf(-sx[j]));
        float py = 1.f / (1.f + __expf(-sy[j]));
        psi[j] = pack2(px, py);
    }

    // ---- out[c] = x[c] * psi : lane quarter q writes channels [16q,16q+16) ----
    const u64* xq = x2 + (size_t)(16 * q) * HALFV;
    u64*       oq = o2 + (size_t)(16 * q) * HALFV;
    #pragma unroll 4
    for (int c = 0; c < 16; c++) {
        size_t base = (size_t)c * HALFV;
        #pragma unroll
        for (int j = 0; j < 4; j++) {
            oq[base + 8 * j] = fmul2(xq[base + 8 * j], psi[j]);
        }
    }
}

extern "C" void kernel_launch(void* const* d_in, const int* in_sizes, int n_in,
                              void* d_out, int out_size)
{
    const float* x    = (const float*)d_in[0];
    const float* g    = (const float*)d_in[1];
    const float* Wg   = (const float*)d_in[2];
    const float* Wx   = (const float*)d_in[3];
    const float* Wpsi = (const float*)d_in[4];
    float* out = (float*)d_out;

    // 262144 voxel pairs / 32 pairs-per-warp = 8192 warps = 1024 blocks
    attn_gate_kernel<<<1024, 256>>>(x, g, Wg, Wx, Wpsi, out);
}